// round 15
// baseline (speedup 1.0000x reference)
#include <cuda_runtime.h>
#include <cuda_fp16.h>

#define B_   8
#define TGT  256
#define SRC  256
#define DM   512
#define LOGEPS (-18.420680743952367f)

// tf32 gemm smem geometry
#define APW 36                         // A stage pitch (floats): 32 + 4 pad
#define BPW 132                        // B stage pitch (floats): 128 + 4 pad
#define ASTG_B (64 * APW * 4)          // 9216
#define BSTG_B (32 * BPW * 4)          // 16896
#define STG_B (ASTG_B + BSTG_B)        // 26112
#define GEMM_SMEM (3 * STG_B)          // 78336
#define NITER 16

// fused-kernel smem geometry (4-byte words). t-tile=4, et chunk=32 l.
#define TT    4
#define EPW   20                       // et row pitch: 4 uint4 + 1 uint4 pad (16B-aligned)
#define EBUF  (256 * EPW)              // 5120 words per buffer
#define DTW   (TT * 132)               // 528
#define OPW   260
#define FUSED_WORDS (2 * EBUF + DTW + 128 + TT * OPW + 8)  // 11944
#define FUSED_SMEM  (FUSED_WORDS * 4)                      // 47776 B

// scratch (no allocation allowed -> __device__ globals)
__device__ unsigned g_dt[B_ * TGT * (SRC / 2)];  // dec @ W1  [B,T,L] as half2
__device__ unsigned g_et[B_ * SRC * (SRC / 2)];  // enc @ W2  [B,S,L] as half2

__device__ __forceinline__ __half2 tanh2(__half2 x) {
    unsigned xi = *(unsigned*)&x, yi;
    asm("tanh.approx.f16x2 %0, %1;" : "=r"(yi) : "r"(xi));
    return *(__half2*)&yi;
}
__device__ __forceinline__ __half2 uh(unsigned u) { return *(__half2*)&u; }
__device__ __forceinline__ float h2sum(__half2 h) {
    float2 f = __half22float2(h);
    return f.x + f.y;
}
__device__ __forceinline__ void mma_tf32(float* c, const unsigned* a, unsigned b0,
                                         unsigned b1) {
    asm volatile(
        "mma.sync.aligned.m16n8k8.row.col.f32.tf32.tf32.f32 "
        "{%0,%1,%2,%3}, {%4,%5,%6,%7}, {%8,%9}, {%0,%1,%2,%3};"
        : "+f"(c[0]), "+f"(c[1]), "+f"(c[2]), "+f"(c[3])
        : "r"(a[0]), "r"(a[1]), "r"(a[2]), "r"(a[3]), "r"(b0), "r"(b1));
}
__device__ __forceinline__ void cpa16(unsigned dst, const void* src) {
    asm volatile("cp.async.ca.shared.global [%0], [%1], 16;" :: "r"(dst), "l"(src));
}

// ---------------------------------------------------------------------------
// tf32 tensor-core GEMM, fp32 inputs straight from gmem (NO convert kernel).
// z=0: g_dt = dec@W1 ; z=1: g_et = enc@W2. BM=64 BN=128 BK=32.
// Grid (32,2,2)=128 CTAs; 256 threads = 8 warps (2m x 4n); warp tile 32x32.
// 3-stage cp.async ring of fp32 tiles; fragments via conflict-free LDS.32.
// ---------------------------------------------------------------------------
__global__ __launch_bounds__(256) void gemm_kernel(const float* __restrict__ dec,
                                                   const float* __restrict__ enc,
                                                   const float* __restrict__ W1,
                                                   const float* __restrict__ W2) {
    extern __shared__ float smf[];
    int z = blockIdx.z;
    const float* A = z ? enc : dec;
    const float* W = z ? W2 : W1;
    unsigned* C = z ? g_et : g_dt;
    int tid = threadIdx.x;
    int warp = tid >> 5, lane = tid & 31;
    int warp_m = warp >> 2, warp_n = warp & 3;
    int bm = blockIdx.x * 64, bn = blockIdx.y * 128;
    unsigned s_u32 = (unsigned)__cvta_generic_to_shared(smf);

    // cp.async coords: A 64x32 fl (512 chunks, 2/thr), B 32x128 fl (1024, 4/thr)
    int ar0 = tid >> 3, aq0 = (tid & 7) * 4;
    int ar1 = (tid + 256) >> 3, aq1 = ((tid + 256) & 7) * 4;
    const float* srcA0 = A + (bm + ar0) * DM + aq0;
    const float* srcA1 = A + (bm + ar1) * DM + aq1;
    unsigned dA0 = s_u32 + (ar0 * APW + aq0) * 4;
    unsigned dA1 = s_u32 + (ar1 * APW + aq1) * 4;

#define LOADST(st, k0)                                                        \
    {                                                                         \
        unsigned o = (unsigned)(st) * STG_B;                                  \
        cpa16(dA0 + o, srcA0 + (k0));                                         \
        cpa16(dA1 + o, srcA1 + (k0));                                         \
        _Pragma("unroll") for (int i = 0; i < 4; i++) {                       \
            int idx = tid + i * 256;                                          \
            int r = idx >> 5, q = (idx & 31) * 4;                             \
            cpa16(s_u32 + o + ASTG_B + (r * BPW + q) * 4,                     \
                  W + (size_t)((k0) + r) * SRC + bn + q);                     \
        }                                                                     \
        asm volatile("cp.async.commit_group;");                               \
    }

    LOADST(0, 0);
    LOADST(1, 32);

    float acc[2][4][4] = {};
    for (int it = 0; it < NITER; it++) {
        asm volatile("cp.async.wait_group 1;");
        __syncthreads();
        int nxt = it + 2;
        if (nxt < NITER) {
            LOADST(nxt % 3, nxt * 32);
        } else {
            asm volatile("cp.async.commit_group;");
        }
        const float* sa = smf + (it % 3) * (STG_B / 4);
        const float* sb = sa + ASTG_B / 4;
#pragma unroll
        for (int ks = 0; ks < 4; ks++) {
            int kc = ks * 8 + (lane & 3);
            unsigned a[2][4], b[4][2];
#pragma unroll
            for (int mt = 0; mt < 2; mt++) {
                int r = warp_m * 32 + mt * 16 + (lane >> 2);
                a[mt][0] = __float_as_uint(sa[r * APW + kc]);
                a[mt][1] = __float_as_uint(sa[(r + 8) * APW + kc]);
                a[mt][2] = __float_as_uint(sa[r * APW + kc + 4]);
                a[mt][3] = __float_as_uint(sa[(r + 8) * APW + kc + 4]);
            }
#pragma unroll
            for (int nt = 0; nt < 4; nt++) {
                int n = warp_n * 32 + nt * 8 + (lane >> 2);
                int k = ks * 8 + (lane & 3);
                b[nt][0] = __float_as_uint(sb[k * BPW + n]);
                b[nt][1] = __float_as_uint(sb[(k + 4) * BPW + n]);
            }
#pragma unroll
            for (int mt = 0; mt < 2; mt++)
#pragma unroll
                for (int nt = 0; nt < 4; nt++)
                    mma_tf32(acc[mt][nt], a[mt], b[nt][0], b[nt][1]);
        }
        __syncthreads();
    }
    // epilogue: fp32 -> half2 stores (same fragment layout as m16n8k16)
#pragma unroll
    for (int rt = 0; rt < 2; rt++) {
        int r0 = bm + warp_m * 32 + rt * 16 + (lane >> 2);
#pragma unroll
        for (int ct = 0; ct < 4; ct++) {
            int colpair = (bn + warp_n * 32 + ct * 8) / 2 + (lane & 3);
            __half2 h01 = __floats2half2_rn(acc[rt][ct][0], acc[rt][ct][1]);
            __half2 h23 = __floats2half2_rn(acc[rt][ct][2], acc[rt][ct][3]);
            C[r0 * (SRC / 2) + colpair] = *(unsigned*)&h01;
            C[(r0 + 8) * (SRC / 2) + colpair] = *(unsigned*)&h23;
        }
    }
#undef LOADST
}

// ---------------------------------------------------------------------------
// FUSED scores + masked log_softmax + transpose (R14, unchanged — passed).
// Block = (b, 4-t-row tile); grid (64,8)=512 blocks; 256 threads = 8 warps.
// Warp w: t-row tr=w&3, s-half sh=w>>2. Thread owns 4 s values.
// ---------------------------------------------------------------------------
__global__ __launch_bounds__(256) void fused_kernel(const float* __restrict__ vt,
                                                    const int* __restrict__ lens,
                                                    float* __restrict__ out) {
    extern __shared__ unsigned shm[];
    unsigned* s_et = shm;                       // [2][256][EPW]
    unsigned* s_dt = shm + 2 * EBUF;            // [TT][132]
    unsigned* s_vt = s_dt + DTW;                // [128]
    float*    s_o  = (float*)(s_vt + 128);      // [TT][OPW]
    float*    s_red = s_o + TT * OPW;           // [2][4]
    int tid = threadIdx.x;
    int tx = tid & 31, w = tid >> 5;
    int tr = w & 3, sh = w >> 2;
    int b = blockIdx.y, t0 = blockIdx.x * TT;
    const unsigned* dtp = g_dt + (b * TGT + t0) * 128;
    const unsigned* etp = g_et + b * SRC * 128;
    unsigned et_u32 = (unsigned)__cvta_generic_to_shared(s_et);

    if (tid < 128) {
        int r = tid >> 5, q = tid & 31;
        *(uint4*)&s_dt[r * 132 + q * 4] = *(const uint4*)&dtp[r * 128 + q * 4];
    } else {
        int i = tid - 128;
        __half2 h = __floats2half2_rn(vt[2 * i], vt[2 * i + 1]);
        s_vt[i] = *(unsigned*)&h;
    }

#define ET_LOAD(buf, c)                                                       \
    {                                                                         \
        _Pragma("unroll") for (int i = 0; i < 4; i++) {                       \
            int idx = tid + i * 256;                                          \
            int r = idx >> 2, q = idx & 3;                                    \
            cpa16(et_u32 + ((buf) * EBUF + r * EPW + q * 4) * 4,              \
                  etp + r * 128 + (c) * 16 + q * 4);                          \
        }                                                                     \
        asm volatile("cp.async.commit_group;");                               \
    }

    ET_LOAD(0, 0);
    asm volatile("cp.async.wait_group 0;");
    __syncthreads();

    float accf[4] = {};
    for (int c = 0; c < 8; c++) {
        if (c < 7) ET_LOAD((c + 1) & 1, c + 1);
        __half2 acch[4];
#pragma unroll
        for (int j = 0; j < 4; j++) acch[j] = __float2half2_rn(0.f);
        const uint4* dt4 = (const uint4*)&s_dt[tr * 132];
        const uint4* vt4 = (const uint4*)s_vt;
        const unsigned* eb = s_et + (c & 1) * EBUF;
#pragma unroll
        for (int u = 0; u < 4; u++) {
            uint4 dv = dt4[c * 4 + u];
            uint4 vv = vt4[c * 4 + u];
#pragma unroll
            for (int j = 0; j < 4; j++) {
                int s = sh * 128 + tx + 32 * j;
                uint4 ev = *(const uint4*)&eb[s * EPW + u * 4];
#define STEP(U)                                                               \
    acch[j] = __hfma2(tanh2(__hadd2(uh(dv.U), uh(ev.U))), uh(vv.U), acch[j]);
                STEP(x) STEP(y) STEP(z) STEP(w)
#undef STEP
            }
        }
#pragma unroll
        for (int j = 0; j < 4; j++) accf[j] += h2sum(acch[j]);
        if (c < 7) asm volatile("cp.async.wait_group 0;");
        __syncthreads();
    }

    int len = lens[b];
    float sum = 0.f;
#pragma unroll
    for (int j = 0; j < 4; j++) {
        if (sh * 128 + tx + 32 * j >= len) accf[j] += LOGEPS;
        sum += __expf(accf[j]);
    }
#pragma unroll
    for (int o = 16; o; o >>= 1) sum += __shfl_xor_sync(0xffffffffu, sum, o);
    if (tx == 0) s_red[sh * 4 + tr] = sum;
    __syncthreads();
    float lse = logf(s_red[tr] + s_red[4 + tr]);
#pragma unroll
    for (int j = 0; j < 4; j++)
        s_o[tr * OPW + sh * 128 + tx + 32 * j] = accf[j] - lse;
    __syncthreads();

    float* op = out + b * SRC * TGT;
#pragma unroll
    for (int i = 0; i < 4; i++) {
        int idx = tid + i * 256;
        int t = idx & 3, s = idx >> 2;
        op[s * TGT + t0 + t] = s_o[t * OPW + s];
    }
#undef ET_LOAD
}

extern "C" void kernel_launch(void* const* d_in, const int* in_sizes, int n_in,
                              void* d_out, int out_size) {
    const float* dec  = (const float*)d_in[0];
    const float* enc  = (const float*)d_in[1];
    const int*   lens = (const int*)d_in[2];
    const float* W1   = (const float*)d_in[3];
    const float* W2   = (const float*)d_in[4];
    const float* vt   = (const float*)d_in[5];
    float*       out  = (float*)d_out;

    cudaFuncSetAttribute(gemm_kernel, cudaFuncAttributeMaxDynamicSharedMemorySize,
                         GEMM_SMEM);
    gemm_kernel<<<dim3(32, 2, 2), 256, GEMM_SMEM>>>(dec, enc, W1, W2);

    cudaFuncSetAttribute(fused_kernel, cudaFuncAttributeMaxDynamicSharedMemorySize,
                         FUSED_SMEM);
    fused_kernel<<<dim3(64, 8), 256, FUSED_SMEM>>>(vt, lens, out);
}

// round 16
// speedup vs baseline: 1.2204x; 1.2204x over previous
#include <cuda_runtime.h>
#include <cuda_fp16.h>

#define B_   8
#define TGT  256
#define SRC  256
#define DM   512
#define PITCH 132           // half2 words per smem row (scores kernel)
#define LOGEPS (-18.420680743952367f)

#define APITCH 40    // halves; 80B rows -> conflict-free ldmatrix
#define BPITCH 136   // halves; 272B rows -> conflict-free ldmatrix.trans
#define STAGES 6
#define NITER 16
#define A_TILE_H 2560                 // 64*40 halves  = 5120 B
#define B_TILE_H 4352                 // 32*136 halves = 8704 B
#define STAGE_BYTES ((A_TILE_H + B_TILE_H) * 2)  // 13824
#define A_Z_H (32 * 16 * A_TILE_H)    // 1310720 halves per z
#define A_TOT_H (2 * A_Z_H)           // 2621440
#define B_Z_H (2 * 16 * B_TILE_H)     // 139264

// scratch (no allocation allowed -> __device__ globals)
__device__ unsigned g_h16[1449984];              // tiled fp16 images (half2 words)
__device__ unsigned g_dt[B_ * TGT * (SRC / 2)];  // dec @ W1  [B,T,L] as half2
__device__ unsigned g_et[B_ * SRC * (SRC / 2)];  // enc @ W2  [B,S,L] as half2
__device__ float    g_sc[B_ * TGT * SRC];        // scores    [B,T,S] fp32

__device__ __forceinline__ __half2 tanh2(__half2 x) {
    unsigned xi = *(unsigned*)&x, yi;
    asm("tanh.approx.f16x2 %0, %1;" : "=r"(yi) : "r"(xi));
    return *(__half2*)&yi;
}
// Pade(5,4) tanh on FMA/ALU pipes only (no MUFU):
// tanh x ~ x(945+105z+z^2)/(945+420z+15z^2), z=x^2, |x| clamped to 4.7,
// reciprocal via integer magic seed + 2 half2 Newton steps, result clamped to [-1,1].
__device__ __forceinline__ __half2 ptanh2(__half2 x) {
    const __half2 cP  = __floats2half2_rn(4.7f, 4.7f);
    const __half2 cN  = __floats2half2_rn(-4.7f, -4.7f);
    const __half2 c105 = __floats2half2_rn(105.f, 105.f);
    const __half2 c945 = __floats2half2_rn(945.f, 945.f);
    const __half2 cm15 = __floats2half2_rn(-15.f, -15.f);
    const __half2 cm420 = __floats2half2_rn(-420.f, -420.f);
    const __half2 cm945 = __floats2half2_rn(-945.f, -945.f);
    const __half2 two = __floats2half2_rn(2.f, 2.f);
    const __half2 one = __floats2half2_rn(1.f, 1.f);
    const __half2 mone = __floats2half2_rn(-1.f, -1.f);
    __half2 xc = __hmin2(__hmax2(x, cN), cP);
    __half2 z = __hmul2(xc, xc);
    __half2 num = __hmul2(__hfma2(__hadd2(z, c105), z, c945), xc);
    __half2 nden = __hfma2(__hfma2(z, cm15, cm420), z, cm945);  // -(den), den>0
    unsigned db = (*(unsigned*)&nden) ^ 0x80008000u;            // bits of +den
    unsigned rb = 0x77A477A4u - db;                             // rcp seed
    __half2 r = *(__half2*)&rb;
    r = __hmul2(r, __hfma2(nden, r, two));
    r = __hmul2(r, __hfma2(nden, r, two));
    __half2 y = __hmul2(num, r);
    return __hmin2(__hmax2(y, mone), one);
}
__device__ __forceinline__ __half2 uh(unsigned u) { return *(__half2*)&u; }
__device__ __forceinline__ float h2sum(__half2 h) {
    float2 f = __half22float2(h);
    return f.x + f.y;
}
__device__ __forceinline__ void ldsm4(unsigned& r0, unsigned& r1, unsigned& r2,
                                      unsigned& r3, unsigned addr) {
    asm volatile("ldmatrix.sync.aligned.m8n8.x4.shared.b16 {%0,%1,%2,%3}, [%4];"
                 : "=r"(r0), "=r"(r1), "=r"(r2), "=r"(r3) : "r"(addr));
}
__device__ __forceinline__ void ldsm4t(unsigned& r0, unsigned& r1, unsigned& r2,
                                       unsigned& r3, unsigned addr) {
    asm volatile("ldmatrix.sync.aligned.m8n8.x4.trans.shared.b16 {%0,%1,%2,%3}, [%4];"
                 : "=r"(r0), "=r"(r1), "=r"(r2), "=r"(r3) : "r"(addr));
}
__device__ __forceinline__ void mma16816(float* c, const unsigned* a, unsigned b0,
                                         unsigned b1) {
    asm volatile(
        "mma.sync.aligned.m16n8k16.row.col.f32.f16.f16.f32 "
        "{%0,%1,%2,%3}, {%4,%5,%6,%7}, {%8,%9}, {%0,%1,%2,%3};"
        : "+f"(c[0]), "+f"(c[1]), "+f"(c[2]), "+f"(c[3])
        : "r"(a[0]), "r"(a[1]), "r"(a[2]), "r"(a[3]), "r"(b0), "r"(b1));
}
__device__ __forceinline__ void bulk_cp(unsigned dst, const void* src, unsigned bytes,
                                        unsigned mbar) {
    asm volatile(
        "cp.async.bulk.shared::cluster.global.mbarrier::complete_tx::bytes "
        "[%0], [%1], %2, [%3];"
        :: "r"(dst), "l"(src), "r"(bytes), "r"(mbar) : "memory");
}
__device__ __forceinline__ void mbar_expect(unsigned mbar, unsigned bytes) {
    asm volatile("mbarrier.arrive.expect_tx.shared.b64 _, [%0], %1;"
                 :: "r"(mbar), "r"(bytes) : "memory");
}
__device__ __forceinline__ void mbar_wait(unsigned mbar, int phase) {
    asm volatile(
        "{\n\t.reg .pred P;\n\t"
        "W_%=:\n\t"
        "mbarrier.try_wait.parity.acquire.cta.shared::cta.b64 P, [%0], %1, 0x989680;\n\t"
        "@P bra.uni D_%=;\n\t"
        "bra.uni W_%=;\n\t"
        "D_%=:\n\t}"
        :: "r"(mbar), "r"(phase) : "memory");
}

// ---------------------------------------------------------------------------
// fp32 -> fp16 convert into PRE-TILED images matching gemm smem stage layout.
// ---------------------------------------------------------------------------
__global__ __launch_bounds__(256) void convert_kernel(const float* __restrict__ dec,
                                                      const float* __restrict__ enc,
                                                      const float* __restrict__ W1,
                                                      const float* __restrict__ W2) {
    int g = blockIdx.x * 256 + threadIdx.x;
    __half* dsth = (__half*)g_h16;
    const float* src;
    size_t off;
    if (g < 262144) {  // A groups
        int chunk = g & 3, row = (g >> 2) & 63, k0 = (g >> 8) & 15;
        int im = (g >> 12) & 31, z = g >> 17;
        src = (z ? enc : dec) + ((im * 64 + row) * DM + k0 * 32 + chunk * 8);
        off = (size_t)z * A_Z_H + (im * 16 + k0) * A_TILE_H + row * APITCH + chunk * 8;
    } else {  // B groups
        int h = g - 262144;
        int chunk = h & 15, row = (h >> 4) & 31, k0 = (h >> 9) & 15;
        int in = (h >> 13) & 1, z = h >> 14;
        src = (z ? W2 : W1) + ((k0 * 32 + row) * SRC + in * 128 + chunk * 8);
        off = A_TOT_H + (size_t)z * B_Z_H + (in * 16 + k0) * B_TILE_H + row * BPITCH +
              chunk * 8;
    }
    float4 v0 = ((const float4*)src)[0];
    float4 v1 = ((const float4*)src)[1];
    __half2 h0 = __floats2half2_rn(v0.x, v0.y);
    __half2 h1 = __floats2half2_rn(v0.z, v0.w);
    __half2 h2 = __floats2half2_rn(v1.x, v1.y);
    __half2 h3 = __floats2half2_rn(v1.z, v1.w);
    *(uint4*)(dsth + off) = make_uint4(*(unsigned*)&h0, *(unsigned*)&h1,
                                       *(unsigned*)&h2, *(unsigned*)&h3);
}

// ---------------------------------------------------------------------------
// Tensor-core GEMM, cp.async.bulk 6-stage mbarrier pipeline (R10, unchanged).
// ---------------------------------------------------------------------------
__global__ __launch_bounds__(256) void gemm_kernel() {
    extern __shared__ __half sm_h[];
    __shared__ unsigned long long mbar[STAGES];
    int z = blockIdx.z;
    const __half* Abase = (const __half*)g_h16 + (size_t)z * A_Z_H +
                          blockIdx.x * 16 * A_TILE_H;
    const __half* Bbase = (const __half*)g_h16 + A_TOT_H + (size_t)z * B_Z_H +
                          blockIdx.y * 16 * B_TILE_H;
    unsigned* C = z ? g_et : g_dt;
    int tid = threadIdx.x;
    int warp = tid >> 5, lane = tid & 31;
    int warp_m = warp >> 2, warp_n = warp & 3;
    int bm = blockIdx.x * 64, bn = blockIdx.y * 128;

    unsigned smem_u32 = (unsigned)__cvta_generic_to_shared(sm_h);
    unsigned mbar_u32 = (unsigned)__cvta_generic_to_shared(mbar);

    if (tid == 0) {
#pragma unroll
        for (int s = 0; s < STAGES; s++)
            asm volatile("mbarrier.init.shared.b64 [%0], 1;"
                         :: "r"(mbar_u32 + 8 * s) : "memory");
        asm volatile("fence.proxy.async.shared::cta;" ::: "memory");
    }
    __syncthreads();
    if (tid == 0) {
#pragma unroll
        for (int s = 0; s < STAGES; s++) {
            unsigned mb = mbar_u32 + 8 * s;
            unsigned so = smem_u32 + s * STAGE_BYTES;
            mbar_expect(mb, STAGE_BYTES);
            bulk_cp(so, Abase + s * A_TILE_H, A_TILE_H * 2, mb);
            bulk_cp(so + A_TILE_H * 2, Bbase + s * B_TILE_H, B_TILE_H * 2, mb);
        }
    }

    int lm_r = lane & 15, lm_c = (lane >> 4) * 8;
    unsigned a_lm = smem_u32 + ((warp_m * 32 + lm_r) * APITCH + lm_c) * 2;
    unsigned b_lm = smem_u32 + (64 * APITCH + lm_r * BPITCH + warp_n * 32 + lm_c) * 2;

    float acc[2][4][4] = {};
    int st = 0, ph = 0;
    for (int it = 0; it < NITER; it++) {
        mbar_wait(mbar_u32 + 8 * st, ph);
        unsigned so = (unsigned)st * STAGE_BYTES;
#pragma unroll
        for (int ks = 0; ks < 2; ks++) {
            unsigned a0[4], a1[4], b0[4], b1[4];
            ldsm4(a0[0], a0[1], a0[2], a0[3], a_lm + so + ks * 32);
            ldsm4(a1[0], a1[1], a1[2], a1[3], a_lm + so + ks * 32 + 16 * APITCH * 2);
            ldsm4t(b0[0], b0[1], b0[2], b0[3], b_lm + so + ks * 16 * BPITCH * 2);
            ldsm4t(b1[0], b1[1], b1[2], b1[3], b_lm + so + ks * 16 * BPITCH * 2 + 32);
            mma16816(acc[0][0], a0, b0[0], b0[1]);
            mma16816(acc[0][1], a0, b0[2], b0[3]);
            mma16816(acc[0][2], a0, b1[0], b1[1]);
            mma16816(acc[0][3], a0, b1[2], b1[3]);
            mma16816(acc[1][0], a1, b0[0], b0[1]);
            mma16816(acc[1][1], a1, b0[2], b0[3]);
            mma16816(acc[1][2], a1, b1[0], b1[1]);
            mma16816(acc[1][3], a1, b1[2], b1[3]);
        }
        __syncthreads();
        int nxt = it + STAGES;
        if (tid == 0 && nxt < NITER) {
            unsigned mb = mbar_u32 + 8 * st;
            unsigned sd = smem_u32 + st * STAGE_BYTES;
            mbar_expect(mb, STAGE_BYTES);
            bulk_cp(sd, Abase + nxt * A_TILE_H, A_TILE_H * 2, mb);
            bulk_cp(sd + A_TILE_H * 2, Bbase + nxt * B_TILE_H, B_TILE_H * 2, mb);
        }
        if (++st == STAGES) { st = 0; ph ^= 1; }
    }
#pragma unroll
    for (int rt = 0; rt < 2; rt++) {
        int r0 = bm + warp_m * 32 + rt * 16 + (lane >> 2);
#pragma unroll
        for (int ct = 0; ct < 4; ct++) {
            int colpair = (bn + warp_n * 32 + ct * 8) / 2 + (lane & 3);
            __half2 h01 = __floats2half2_rn(acc[rt][ct][0], acc[rt][ct][1]);
            __half2 h23 = __floats2half2_rn(acc[rt][ct][2], acc[rt][ct][3]);
            C[r0 * (SRC / 2) + colpair] = *(unsigned*)&h01;
            C[(r0 + 8) * (SRC / 2) + colpair] = *(unsigned*)&h23;
        }
    }
}

// ---------------------------------------------------------------------------
// scores[b,t,s] = sum_l vt[l] * tanh(dt[b,t,l] + et[b,s,l]), f16x2 math.
// Pipe-split: fields x,y,z use MUFU tanh2; field w uses FMA/ALU Pade tanh.
// 32x32 tile, 2x2 micro-tile, fp32 flush every 64 l.
// ---------------------------------------------------------------------------
__global__ __launch_bounds__(256) void scores_kernel(const float* __restrict__ vt) {
    __shared__ unsigned sdt[32 * PITCH];
    __shared__ unsigned set[32 * PITCH];
    __shared__ unsigned svt[128];
    int tid = threadIdx.x;
    int b = blockIdx.z, t0 = blockIdx.y * 32, s0 = blockIdx.x * 32;
    const unsigned* dtp = g_dt + (b * TGT + t0) * (SRC / 2);
    const unsigned* etp = g_et + (b * SRC + s0) * (SRC / 2);
#pragma unroll
    for (int i = 0; i < 4; i++) {
        int idx = tid + i * 256;  // 1024 uint4 per tile
        int r = idx >> 5, q = (idx & 31) * 4;
        *(uint4*)&sdt[r * PITCH + q] = *(const uint4*)&dtp[r * (SRC / 2) + q];
        *(uint4*)&set[r * PITCH + q] = *(const uint4*)&etp[r * (SRC / 2) + q];
    }
    if (tid < 128) {
        __half2 h = __floats2half2_rn(vt[2 * tid], vt[2 * tid + 1]);
        svt[tid] = *(unsigned*)&h;
    }
    __syncthreads();

    int tx = tid & 15, ty = tid >> 4;
    const uint4* pv = (const uint4*)svt;
    const uint4* dA = (const uint4*)(sdt + ty * PITCH);
    const uint4* dB = (const uint4*)(sdt + (ty + 16) * PITCH);
    const uint4* eA = (const uint4*)(set + tx * PITCH);
    const uint4* eB = (const uint4*)(set + (tx + 16) * PITCH);
    float a00 = 0.f, a01 = 0.f, a10 = 0.f, a11 = 0.f;
    for (int p = 0; p < 4; p++) {  // 4 phases x 8 chunks x 4 half2 = 256 l
        __half2 s00 = __float2half2_rn(0.f), s01 = s00, s10 = s00, s11 = s00;
#pragma unroll
        for (int c = p * 8; c < p * 8 + 8; c++) {
            uint4 vv = pv[c];
            uint4 x0 = dA[c], x1 = dB[c];
            uint4 y0 = eA[c], y1 = eB[c];
#define STEPM(U)                                                \
    {                                                           \
        __half2 v = uh(vv.U);                                   \
        __half2 xa = uh(x0.U), xb = uh(x1.U);                   \
        __half2 ya = uh(y0.U), yb = uh(y1.U);                   \
        s00 = __hfma2(tanh2(__hadd2(xa, ya)), v, s00);          \
        s01 = __hfma2(tanh2(__hadd2(xa, yb)), v, s01);          \
        s10 = __hfma2(tanh2(__hadd2(xb, ya)), v, s10);          \
        s11 = __hfma2(tanh2(__hadd2(xb, yb)), v, s11);          \
    }
#define STEPP(U)                                                \
    {                                                           \
        __half2 v = uh(vv.U);                                   \
        __half2 xa = uh(x0.U), xb = uh(x1.U);                   \
        __half2 ya = uh(y0.U), yb = uh(y1.U);                   \
        s00 = __hfma2(ptanh2(__hadd2(xa, ya)), v, s00);         \
        s01 = __hfma2(ptanh2(__hadd2(xa, yb)), v, s01);         \
        s10 = __hfma2(ptanh2(__hadd2(xb, ya)), v, s10);         \
        s11 = __hfma2(ptanh2(__hadd2(xb, yb)), v, s11);         \
    }
            STEPM(x) STEPM(y) STEPM(z) STEPP(w)
#undef STEPM
#undef STEPP
        }
        a00 += h2sum(s00);
        a01 += h2sum(s01);
        a10 += h2sum(s10);
        a11 += h2sum(s11);
    }
    float* sc = g_sc + (b * TGT + t0) * SRC + s0;
    sc[ty * SRC + tx] = a00;
    sc[ty * SRC + tx + 16] = a01;
    sc[(ty + 16) * SRC + tx] = a10;
    sc[(ty + 16) * SRC + tx + 16] = a11;
}

// ---------------------------------------------------------------------------
// masked log_softmax over s + transpose to out[b,s,t].
// Scores bounded (|score| <= sum|vt| ~ 8) -> skip the max pass.
// grid (16 t-tiles, 8 b), 512 threads, one warp per t-row (16 rows/block).
// ---------------------------------------------------------------------------
__global__ __launch_bounds__(512) void softmax_kernel(const int* __restrict__ lens,
                                                      float* __restrict__ out) {
    __shared__ float sm[16][260];
    __shared__ float slse[16];
    int tid = threadIdx.x;
    int t0 = blockIdx.x * 16, b = blockIdx.y;
    int len = lens[b];
    const float* scp = g_sc + (b * TGT + t0) * SRC;
#pragma unroll
    for (int i = 0; i < 2; i++) {
        int idx = tid + i * 512;  // 1024 float4 = 16 rows x 64 chunks
        int r = idx >> 6, s4 = (idx & 63) * 4;
        float4 v = *(const float4*)&scp[r * SRC + s4];
        if (s4 + 3 >= len) {
            if (s4 + 0 >= len) v.x += LOGEPS;
            if (s4 + 1 >= len) v.y += LOGEPS;
            if (s4 + 2 >= len) v.z += LOGEPS;
            if (s4 + 3 >= len) v.w += LOGEPS;
        }
        *(float4*)&sm[r][s4] = v;
    }
    __syncthreads();
    int w = tid >> 5, lane = tid & 31;
    {
        float sum = 0.f;
#pragma unroll
        for (int j = 0; j < 8; j++) sum += __expf(sm[w][lane + 32 * j]);
#pragma unroll
        for (int o = 16; o; o >>= 1) sum += __shfl_xor_sync(0xffffffffu, sum, o);
        if (lane == 0) slse[w] = logf(sum);
    }
    __syncthreads();
    float* op = out + b * SRC * TGT;  // out[b][s][t]
#pragma unroll
    for (int i = 0; i < 8; i++) {
        int idx = tid + i * 512;
        int t = idx & 15, s = idx >> 4;
        op[s * TGT + t0 + t] = sm[t][s] - slse[t];
    }
}

extern "C" void kernel_launch(void* const* d_in, const int* in_sizes, int n_in,
                              void* d_out, int out_size) {
    const float* dec  = (const float*)d_in[0];
    const float* enc  = (const float*)d_in[1];
    const int*   lens = (const int*)d_in[2];
    const float* W1   = (const float*)d_in[3];
    const float* W2   = (const float*)d_in[4];
    const float* vt   = (const float*)d_in[5];
    float*       out  = (float*)d_out;

    convert_kernel<<<1152, 256>>>(dec, enc, W1, W2);

    constexpr int GEMM_SMEM = STAGES * STAGE_BYTES;  // 82944 B
    cudaFuncSetAttribute(gemm_kernel, cudaFuncAttributeMaxDynamicSharedMemorySize,
                         GEMM_SMEM);
    gemm_kernel<<<dim3(32, 2, 2), 256, GEMM_SMEM>>>();

    scores_kernel<<<dim3(8, 8, 8), 256>>>(vt);
    softmax_kernel<<<dim3(16, 8), 512>>>(lens, out);
}